// round 6
// baseline (speedup 1.0000x reference)
#include <cuda_runtime.h>

// Problem dims (fixed by reference)
#define Bb 4
#define Ss 2048
#define Dd 1024
#define Hh 16
#define DEPTH 64
#define BS (Bb * Ss)   // 8192
#define BH (Bb * Hh)   // 64

// Scratch (allocation-free rule: __device__ globals)
__device__ float g_Q[(size_t)BH * Ss * DEPTH];     // [B,H,S,64]
__device__ float g_K[(size_t)BH * Ss * DEPTH];
__device__ float g_V[(size_t)BH * Ss * DEPTH];
__device__ float g_ctx[(size_t)BS * Dd];           // [B,S,D]
__device__ float g_attn[(size_t)BH * Ss * Ss];     // fallback attn buffer (1 GB)

// ---------------------------------------------------------------------------
// Dense GEMM + bias:  Y = X[8192,1024] @ W[1024,1024] + bias
// split_heads=1 -> write into [B,H,S,64] head layout; else plain [8192,1024].
// 64x64 tile, BK=16, 256 threads, 4x4 accum per thread.
// ---------------------------------------------------------------------------
__global__ void gemm_bias_kernel(const float* __restrict__ X,
                                 const float* __restrict__ W,
                                 const float* __restrict__ bias,
                                 float* __restrict__ Y,
                                 int split_heads) {
    __shared__ float As[64][17];   // [m][k], padded
    __shared__ float Bs[16][64];   // [k][n]

    int tid = threadIdx.x;
    int tx = tid & 15, ty = tid >> 4;
    int m0 = blockIdx.y * 64;
    int n0 = blockIdx.x * 64;

    float acc[4][4] = {};

    for (int k0 = 0; k0 < Dd; k0 += 16) {
        #pragma unroll
        for (int i = 0; i < 4; i++) {
            int idx = tid + i * 256;              // 0..1023
            int m = idx >> 4, k = idx & 15;
            As[m][k] = X[(size_t)(m0 + m) * Dd + k0 + k];
        }
        #pragma unroll
        for (int i = 0; i < 4; i++) {
            int idx = tid + i * 256;
            int k = idx >> 6, n = idx & 63;
            Bs[k][n] = W[(size_t)(k0 + k) * Dd + n0 + n];
        }
        __syncthreads();
        #pragma unroll
        for (int k = 0; k < 16; k++) {
            float a[4], b[4];
            #pragma unroll
            for (int i = 0; i < 4; i++) a[i] = As[ty * 4 + i][k];
            #pragma unroll
            for (int j = 0; j < 4; j++) b[j] = Bs[k][tx * 4 + j];
            #pragma unroll
            for (int i = 0; i < 4; i++)
                #pragma unroll
                for (int j = 0; j < 4; j++) acc[i][j] += a[i] * b[j];
        }
        __syncthreads();
    }

    #pragma unroll
    for (int i = 0; i < 4; i++) {
        int m = m0 + ty * 4 + i;
        int b = m >> 11, s = m & 2047;
        #pragma unroll
        for (int j = 0; j < 4; j++) {
            int n = n0 + tx * 4 + j;
            float v = acc[i][j] + bias[n];
            if (split_heads) {
                int h = n >> 6, d = n & 63;
                g_dummy:;
                ((float*)Y)[(((size_t)(b * Hh + h) * Ss + s) << 6) + d] = v;
            } else {
                Y[(size_t)m * Dd + n] = v;
            }
        }
    }
}

// ---------------------------------------------------------------------------
// logits[bh, sq, sk] = (Q[bh,sq,:] . K[bh,sk,:]) / 8 + mask[sq,sk] * -1e9
// per-batch GEMM M=2048, N=2048, K=64
// ---------------------------------------------------------------------------
__global__ void logits_kernel(const float* __restrict__ mask,
                              float* __restrict__ attn) {
    int bh = blockIdx.z;
    const float* Q = g_Q + (size_t)bh * Ss * DEPTH;
    const float* K = g_K + (size_t)bh * Ss * DEPTH;

    __shared__ float As[64][17];   // Q tile [m][k]
    __shared__ float Bt[64][17];   // K tile [n][k]

    int tid = threadIdx.x;
    int tx = tid & 15, ty = tid >> 4;
    int m0 = blockIdx.y * 64;
    int n0 = blockIdx.x * 64;

    float acc[4][4] = {};

    for (int k0 = 0; k0 < DEPTH; k0 += 16) {
        #pragma unroll
        for (int i = 0; i < 4; i++) {
            int idx = tid + i * 256;
            int m = idx >> 4, k = idx & 15;
            As[m][k] = Q[(size_t)(m0 + m) * DEPTH + k0 + k];
            Bt[m][k] = K[(size_t)(n0 + m) * DEPTH + k0 + k];
        }
        __syncthreads();
        #pragma unroll
        for (int k = 0; k < 16; k++) {
            float a[4], b[4];
            #pragma unroll
            for (int i = 0; i < 4; i++) a[i] = As[ty * 4 + i][k];
            #pragma unroll
            for (int j = 0; j < 4; j++) b[j] = Bt[tx * 4 + j][k];
            #pragma unroll
            for (int i = 0; i < 4; i++)
                #pragma unroll
                for (int j = 0; j < 4; j++) acc[i][j] += a[i] * b[j];
        }
        __syncthreads();
    }

    #pragma unroll
    for (int i = 0; i < 4; i++) {
        int sq = m0 + ty * 4 + i;
        #pragma unroll
        for (int j = 0; j < 4; j++) {
            int sk = n0 + tx * 4 + j;
            float v = acc[i][j] * 0.125f + mask[(size_t)sq * Ss + sk] * -1e9f;
            attn[((size_t)bh * Ss + sq) * Ss + sk] = v;
        }
    }
}

// ---------------------------------------------------------------------------
// Row softmax over the last dim (2048). One 256-thread block per row.
// ---------------------------------------------------------------------------
__global__ void softmax_kernel(float* __restrict__ attn) {
    size_t row = blockIdx.x;
    float* p = attn + row * Ss;
    int tid = threadIdx.x;

    float v[8];
    float mx = -1e30f;
    #pragma unroll
    for (int i = 0; i < 8; i++) {
        v[i] = p[tid + i * 256];
        mx = fmaxf(mx, v[i]);
    }

    __shared__ float red[256];
    red[tid] = mx;
    __syncthreads();
    for (int s = 128; s > 0; s >>= 1) {
        if (tid < s) red[tid] = fmaxf(red[tid], red[tid + s]);
        __syncthreads();
    }
    mx = red[0];
    __syncthreads();

    float sum = 0.f;
    #pragma unroll
    for (int i = 0; i < 8; i++) {
        v[i] = __expf(v[i] - mx);
        sum += v[i];
    }
    red[tid] = sum;
    __syncthreads();
    for (int s = 128; s > 0; s >>= 1) {
        if (tid < s) red[tid] += red[tid + s];
        __syncthreads();
    }
    float inv = 1.f / red[0];
    #pragma unroll
    for (int i = 0; i < 8; i++) p[tid + i * 256] = v[i] * inv;
}

// ---------------------------------------------------------------------------
// ctx[b,s,h*64+d] = sum_k attn[bh,s,k] * V[bh,k,d]
// per-batch GEMM M=2048, N=64, K=2048
// ---------------------------------------------------------------------------
__global__ void ctx_kernel(const float* __restrict__ attn) {
    int bh = blockIdx.z;
    int b = bh >> 4, h = bh & 15;
    const float* A = attn + (size_t)bh * Ss * Ss;
    const float* V = g_V + (size_t)bh * Ss * DEPTH;

    __shared__ float As[64][17];   // attn tile [m][k]
    __shared__ float Bs[16][64];   // V tile [k][n]

    int tid = threadIdx.x;
    int tx = tid & 15, ty = tid >> 4;
    int m0 = blockIdx.y * 64;

    float acc[4][4] = {};

    for (int k0 = 0; k0 < Ss; k0 += 16) {
        #pragma unroll
        for (int i = 0; i < 4; i++) {
            int idx = tid + i * 256;
            int m = idx >> 4, k = idx & 15;
            As[m][k] = A[(size_t)(m0 + m) * Ss + k0 + k];
        }
        #pragma unroll
        for (int i = 0; i < 4; i++) {
            int idx = tid + i * 256;
            int k = idx >> 6, n = idx & 63;
            Bs[k][n] = V[(size_t)(k0 + k) * DEPTH + n];
        }
        __syncthreads();
        #pragma unroll
        for (int k = 0; k < 16; k++) {
            float a[4], bb[4];
            #pragma unroll
            for (int i = 0; i < 4; i++) a[i] = As[ty * 4 + i][k];
            #pragma unroll
            for (int j = 0; j < 4; j++) bb[j] = Bs[k][tx * 4 + j];
            #pragma unroll
            for (int i = 0; i < 4; i++)
                #pragma unroll
                for (int j = 0; j < 4; j++) acc[i][j] += a[i] * bb[j];
        }
        __syncthreads();
    }

    #pragma unroll
    for (int i = 0; i < 4; i++) {
        int s = m0 + ty * 4 + i;
        #pragma unroll
        for (int j = 0; j < 4; j++) {
            int d = tx * 4 + j;
            g_ctx[((size_t)(b * Ss + s)) * Dd + h * DEPTH + d] = acc[i][j];
        }
    }
}

// ---------------------------------------------------------------------------
extern "C" void kernel_launch(void* const* d_in, const int* in_sizes, int n_in,
                              void* d_out, int out_size) {
    const float* q    = (const float*)d_in[0];
    const float* k    = (const float*)d_in[1];
    const float* v    = (const float*)d_in[2];
    const float* mask = (const float*)d_in[3];
    const float* Wq   = (const float*)d_in[4];
    const float* bq   = (const float*)d_in[5];
    const float* Wk   = (const float*)d_in[6];
    const float* bk   = (const float*)d_in[7];
    const float* Wv   = (const float*)d_in[8];
    const float* bv   = (const float*)d_in[9];
    const float* Wo   = (const float*)d_in[10];
    const float* bo   = (const float*)d_in[11];
    float* out = (float*)d_out;

    const size_t OUT_ELEMS  = (size_t)BS * Dd;          // 8,388,608
    const size_t ATTN_ELEMS = (size_t)BH * Ss * Ss;     // 268,435,456

    // Reference returns (out, attn): write attn directly into d_out past 'out'
    // when the output covers both; otherwise keep it in scratch.
    float* attnbuf = nullptr;
    cudaGetSymbolAddress((void**)&attnbuf, g_attn);
    if ((size_t)out_size >= OUT_ELEMS + ATTN_ELEMS) attnbuf = out + OUT_ELEMS;

    float* dQ = nullptr; cudaGetSymbolAddress((void**)&dQ, g_Q);
    float* dK = nullptr; cudaGetSymbolAddress((void**)&dK, g_K);
    float* dV = nullptr; cudaGetSymbolAddress((void**)&dV, g_V);
    float* dC = nullptr; cudaGetSymbolAddress((void**)&dC, g_ctx);

    dim3 projGrid(Dd / 64, BS / 64);        // (16, 128)
    gemm_bias_kernel<<<projGrid, 256>>>(q, Wq, bq, dQ, 1);
    gemm_bias_kernel<<<projGrid, 256>>>(k, Wk, bk, dK, 1);
    gemm_bias_kernel<<<projGrid, 256>>>(v, Wv, bv, dV, 1);

    dim3 logGrid(Ss / 64, Ss / 64, BH);     // (32, 32, 64)
    logits_kernel<<<logGrid, 256>>>(mask, attnbuf);

    softmax_kernel<<<BH * Ss, 256>>>(attnbuf);

    dim3 ctxGrid(1, Ss / 64, BH);           // (1, 32, 64)
    ctx_kernel<<<ctxGrid, 256>>>(attnbuf);

    gemm_bias_kernel<<<projGrid, 256>>>(dC, Wo, bo, out, 0);
}

// round 8
// speedup vs baseline: 2.3313x; 2.3313x over previous
#include <cuda_runtime.h>
#include <cuda_bf16.h>
#include <cstdint>

#define Bb 4
#define Ss 2048
#define Dd 1024
#define Hh 16
#define DEPTH 64
#define BS (Bb * Ss)   // 8192
#define BH (Bb * Hh)   // 64

// ---------------- device scratch (allocation-free rule) ----------------
__device__ __nv_bfloat16 g_Wth[(size_t)Dd * Dd];         // W^T hi (reused)
__device__ __nv_bfloat16 g_Wtl[(size_t)Dd * Dd];         // W^T lo
__device__ __nv_bfloat16 g_Qh[(size_t)BH * Ss * DEPTH];  // [bh][s][64]
__device__ __nv_bfloat16 g_Ql[(size_t)BH * Ss * DEPTH];
__device__ __nv_bfloat16 g_Kh[(size_t)BH * Ss * DEPTH];
__device__ __nv_bfloat16 g_Kl[(size_t)BH * Ss * DEPTH];
__device__ __nv_bfloat16 g_Vth[(size_t)BH * DEPTH * Ss]; // V^T [bh][d][s]
__device__ __nv_bfloat16 g_Vtl[(size_t)BH * DEPTH * Ss];
__device__ __nv_bfloat16 g_Ch[(size_t)BS * Dd];          // ctx hi [b,s,1024]
__device__ __nv_bfloat16 g_Cl[(size_t)BS * Dd];
__device__ float g_attn[(size_t)BH * Ss * Ss];           // fallback fp32 attn (1 GB)

// ---------------- mma.sync / ldmatrix helpers (sm_80+ PTX, no 'a' needed) ----
__device__ __forceinline__ uint32_t smem_u32(const void* p) {
    uint32_t a;
    asm("{ .reg .u64 t; cvta.to.shared.u64 t, %1; cvt.u32.u64 %0, t; }" : "=r"(a) : "l"(p));
    return a;
}

__device__ __forceinline__ void ldsm_x4(uint32_t* r, uint32_t addr) {
    asm volatile("ldmatrix.sync.aligned.m8n8.x4.shared.b16 {%0,%1,%2,%3}, [%4];"
                 : "=r"(r[0]), "=r"(r[1]), "=r"(r[2]), "=r"(r[3]) : "r"(addr));
}

__device__ __forceinline__ void mma16816(float* d, const uint32_t* a, const uint32_t* b) {
    asm volatile(
        "mma.sync.aligned.m16n8k16.row.col.f32.bf16.bf16.f32 "
        "{%0,%1,%2,%3}, {%4,%5,%6,%7}, {%8,%9}, {%0,%1,%2,%3};"
        : "+f"(d[0]), "+f"(d[1]), "+f"(d[2]), "+f"(d[3])
        : "r"(a[0]), "r"(a[1]), "r"(a[2]), "r"(a[3]), "r"(b[0]), "r"(b[1]));
}

// split 8 fp32 -> 8 bf16 hi + 8 bf16 lo
__device__ __forceinline__ void cvt8(const float* v, uint4& h4, uint4& l4) {
    __align__(16) __nv_bfloat16 h[8];
    __align__(16) __nv_bfloat16 l[8];
    #pragma unroll
    for (int i = 0; i < 8; i++) {
        h[i] = __float2bfloat16(v[i]);
        l[i] = __float2bfloat16(v[i] - __bfloat162float(h[i]));
    }
    h4 = *(uint4*)h;
    l4 = *(uint4*)l;
}

// ---------------- shared HMMA mainloop ----------------
// A: [M rows][K] K-major, tile M=128 (fp32 src ASRC=0 converted inline, else bf16 hi/lo pair).
// B: [N rows][K] K-major bf16 hi/lo, tile NT. K chunks of 64 (128B SW-swizzled rows).
// 3 passes per k16: hi*hi + hi*lo + lo*hi, fp32 accumulate in registers.
template <int NT, int ASRC>
__device__ __forceinline__ void gemm_core(
    const float* __restrict__ Af,
    const __nv_bfloat16* __restrict__ Ah, const __nv_bfloat16* __restrict__ Al, int lda,
    const __nv_bfloat16* __restrict__ Bh, const __nv_bfloat16* __restrict__ Bl, int ldb,
    int m0, int n0, int nChunks, char* smem,
    float (*acc)[4][4])
{
    constexpr int MI     = (NT == 128) ? 4 : 2;
    constexpr int OFF_AL = 16384;
    constexpr int OFF_BH = 32768;
    constexpr int OFF_BL = 32768 + NT * 128;

    const int tid = threadIdx.x, wid = tid >> 5, lane = tid & 31;
    const int wy = (NT == 128) ? (wid >> 2) : (wid >> 1);
    const int wx = (NT == 128) ? (wid & 3)  : (wid & 1);
    const int m0w = wy * MI * 16, n0w = wx * 32;
    const uint32_t sb = smem_u32(smem);

    for (int c = 0; c < nChunks; c++) {
        __syncthreads();
        const int kc = c * 64;

        // stage A (128 rows x 64 k, hi+lo)
        #pragma unroll
        for (int i = 0; i < 4; i++) {
            int idx = tid + i * 256;
            int r = idx >> 3, sg = idx & 7;
            uint32_t off = (uint32_t)r * 128 + (((uint32_t)sg * 16) ^ (((uint32_t)(r & 7)) << 4));
            if (ASRC == 0) {
                const float* src = Af + (size_t)(m0 + r) * lda + kc + sg * 8;
                __align__(16) float v[8];
                *(float4*)v       = *(const float4*)src;
                *(float4*)(v + 4) = *(const float4*)(src + 4);
                uint4 h4, l4; cvt8(v, h4, l4);
                *(uint4*)(smem + off)          = h4;
                *(uint4*)(smem + OFF_AL + off) = l4;
            } else {
                size_t go = (size_t)(m0 + r) * lda + kc + sg * 8;
                *(uint4*)(smem + off)          = *(const uint4*)(Ah + go);
                *(uint4*)(smem + OFF_AL + off) = *(const uint4*)(Al + go);
            }
        }
        // stage B (NT rows x 64 k, hi+lo)
        #pragma unroll
        for (int i = 0; i < NT / 32; i++) {
            int idx = tid + i * 256;
            int r = idx >> 3, sg = idx & 7;
            size_t go = (size_t)(n0 + r) * ldb + kc + sg * 8;
            uint32_t off = (uint32_t)r * 128 + (((uint32_t)sg * 16) ^ (((uint32_t)(r & 7)) << 4));
            *(uint4*)(smem + OFF_BH + off) = *(const uint4*)(Bh + go);
            *(uint4*)(smem + OFF_BL + off) = *(const uint4*)(Bl + go);
        }
        __syncthreads();

        #pragma unroll
        for (int ks = 0; ks < 4; ks++) {
            uint32_t ah[MI][4], al[MI][4];
            #pragma unroll
            for (int mi = 0; mi < MI; mi++) {
                int r = m0w + mi * 16 + (lane & 15);
                uint32_t kb = (uint32_t)ks * 32 + (((uint32_t)(lane >> 4)) << 4);
                uint32_t ad = sb + (uint32_t)r * 128 + (kb ^ (((uint32_t)(r & 7)) << 4));
                ldsm_x4(ah[mi], ad);
                ldsm_x4(al[mi], ad + OFF_AL);
            }
            #pragma unroll
            for (int nb = 0; nb < 2; nb++) {
                int n = n0w + nb * 16 + ((lane >> 4) << 3) + (lane & 7);
                uint32_t kb = (uint32_t)ks * 32 + (((uint32_t)((lane >> 3) & 1)) << 4);
                uint32_t bd = sb + OFF_BH + (uint32_t)n * 128 + (kb ^ (((uint32_t)(n & 7)) << 4));
                uint32_t bh[4], bl[4];
                ldsm_x4(bh, bd);
                ldsm_x4(bl, bd + NT * 128);
                #pragma unroll
                for (int mi = 0; mi < MI; mi++) {
                    mma16816(acc[mi][nb * 2],     ah[mi], bh);
                    mma16816(acc[mi][nb * 2 + 1], ah[mi], bh + 2);
                    mma16816(acc[mi][nb * 2],     ah[mi], bl);
                    mma16816(acc[mi][nb * 2 + 1], ah[mi], bl + 2);
                    mma16816(acc[mi][nb * 2],     al[mi], bh);
                    mma16816(acc[mi][nb * 2 + 1], al[mi], bh + 2);
                }
            }
        }
    }
}

static constexpr int SMEM_128 = 32768 + 2 * 128 * 128;  // 65536
static constexpr int SMEM_64  = 32768 + 2 * 64 * 128;   // 49152

// ---------------- projection GEMM: Y[8192,1024] = A @ W^T + bias ----------------
// mode 0: fp32 out [8192,1024]; mode 1: bf16 hi/lo head layout [bh][s][64];
// mode 2: bf16 hi/lo V^T layout [bh][d][s].
template <int ASRC>
__global__ void __launch_bounds__(256, 2)
proj_kernel(const float* __restrict__ Af,
            const __nv_bfloat16* __restrict__ Ah, const __nv_bfloat16* __restrict__ Al,
            const __nv_bfloat16* __restrict__ Bh, const __nv_bfloat16* __restrict__ Bl,
            const float* __restrict__ bias, float* __restrict__ outF,
            __nv_bfloat16* __restrict__ oH, __nv_bfloat16* __restrict__ oL, int mode)
{
    extern __shared__ char smem[];
    int m0 = blockIdx.y * 128, n0 = blockIdx.x * 128;
    float acc[4][4][4] = {};
    gemm_core<128, ASRC>(Af, Ah, Al, 1024, Bh, Bl, 1024, m0, n0, 16, smem, acc);

    int tid = threadIdx.x, wid = tid >> 5, lane = tid & 31;
    int m0w = (wid >> 2) * 64, n0w = (wid & 3) * 32;
    #pragma unroll
    for (int mi = 0; mi < 4; mi++)
        #pragma unroll
        for (int nj = 0; nj < 4; nj++)
            #pragma unroll
            for (int e = 0; e < 4; e++) {
                int r  = m0 + m0w + mi * 16 + (lane >> 2) + (e >> 1) * 8;
                int cc = n0 + n0w + nj * 8 + (lane & 3) * 2 + (e & 1);
                float v = acc[mi][nj][e] + __ldg(bias + cc);
                if (mode == 0) {
                    outF[(size_t)r * Dd + cc] = v;
                } else {
                    __nv_bfloat16 hv = __float2bfloat16(v);
                    __nv_bfloat16 lv = __float2bfloat16(v - __bfloat162float(hv));
                    int b = r >> 11, s = r & 2047, h = cc >> 6, d = cc & 63;
                    size_t bh = (size_t)(b * Hh + h);
                    size_t idx = (mode == 1) ? ((bh * Ss + s) << 6) + d
                                             : (bh * DEPTH + d) * Ss + s;
                    oH[idx] = hv; oL[idx] = lv;
                }
            }
}

// ---------------- logits: attn[bh,sq,sk] = (Q.K)/8 + mask*-1e9 (fp32) ----------------
__global__ void __launch_bounds__(256, 2)
logits_kernel(const __nv_bfloat16* __restrict__ Qh, const __nv_bfloat16* __restrict__ Ql,
              const __nv_bfloat16* __restrict__ Kh, const __nv_bfloat16* __restrict__ Kl,
              const float* __restrict__ mask, float* __restrict__ attn)
{
    extern __shared__ char smem[];
    int bh = blockIdx.z;
    int m0 = blockIdx.y * 128, n0 = blockIdx.x * 128;
    size_t ho = (size_t)bh * Ss * DEPTH;
    float acc[4][4][4] = {};
    gemm_core<128, 1>(nullptr, Qh + ho, Ql + ho, 64, Kh + ho, Kl + ho, 64,
                      m0, n0, 1, smem, acc);

    int tid = threadIdx.x, wid = tid >> 5, lane = tid & 31;
    int m0w = (wid >> 2) * 64, n0w = (wid & 3) * 32;
    #pragma unroll
    for (int mi = 0; mi < 4; mi++)
        #pragma unroll
        for (int nj = 0; nj < 4; nj++)
            #pragma unroll
            for (int e = 0; e < 4; e++) {
                int sq = m0 + m0w + mi * 16 + (lane >> 2) + (e >> 1) * 8;
                int sk = n0 + n0w + nj * 8 + (lane & 3) * 2 + (e & 1);
                float v = acc[mi][nj][e] * 0.125f
                        + __ldg(mask + (size_t)sq * Ss + sk) * -1e9f;
                attn[((size_t)bh * Ss + sq) * Ss + sk] = v;
            }
}

// ---------------- ctx: P(fp32, converted inline) x V^T -> ctx hi/lo ----------------
__global__ void __launch_bounds__(256, 2)
ctx_kernel(const float* __restrict__ attn,
           const __nv_bfloat16* __restrict__ Vth, const __nv_bfloat16* __restrict__ Vtl,
           __nv_bfloat16* __restrict__ Ch, __nv_bfloat16* __restrict__ Cl)
{
    extern __shared__ char smem[];
    int bh = blockIdx.y;
    int m0 = blockIdx.x * 128;
    size_t ao = (size_t)bh * Ss * Ss;
    size_t vo = (size_t)bh * DEPTH * Ss;
    float acc[2][4][4] = {};
    gemm_core<64, 0>(attn + ao, nullptr, nullptr, 2048, Vth + vo, Vtl + vo, 2048,
                     m0, 0, 32, smem, acc);

    int tid = threadIdx.x, wid = tid >> 5, lane = tid & 31;
    int m0w = (wid >> 1) * 32, n0w = (wid & 1) * 32;
    int b = bh >> 4, h = bh & 15;
    #pragma unroll
    for (int mi = 0; mi < 2; mi++)
        #pragma unroll
        for (int nj = 0; nj < 4; nj++)
            #pragma unroll
            for (int e = 0; e < 4; e++) {
                int s = m0 + m0w + mi * 16 + (lane >> 2) + (e >> 1) * 8;
                int d = n0w + nj * 8 + (lane & 3) * 2 + (e & 1);
                float v = acc[mi][nj][e];
                __nv_bfloat16 hv = __float2bfloat16(v);
                __nv_bfloat16 lv = __float2bfloat16(v - __bfloat162float(hv));
                size_t idx = ((size_t)(b * Ss + s)) * Dd + h * DEPTH + d;
                Ch[idx] = hv; Cl[idx] = lv;
            }
}

// ---------------- W[1024,1024] -> W^T hi/lo (K-major for B operand) ----------------
__global__ void transpose_conv_kernel(const float* __restrict__ W,
                                      __nv_bfloat16* __restrict__ Th,
                                      __nv_bfloat16* __restrict__ Tl)
{
    __shared__ float t[32][33];
    int tx = threadIdx.x, ty = threadIdx.y;
    int x = blockIdx.x * 32 + tx;   // n
    int y = blockIdx.y * 32 + ty;   // k
    t[ty][tx] = W[(size_t)y * Dd + x];
    __syncthreads();
    int n = blockIdx.x * 32 + ty;
    int k = blockIdx.y * 32 + tx;
    float v = t[tx][ty];
    __nv_bfloat16 hv = __float2bfloat16(v);
    Th[(size_t)n * Dd + k] = hv;
    Tl[(size_t)n * Dd + k] = __float2bfloat16(v - __bfloat162float(hv));
}

// ---------------- softmax (fp32 in/out) ----------------
__global__ void softmax_kernel(float* __restrict__ attn) {
    size_t row = blockIdx.x;
    float* p = attn + row * Ss;
    int tid = threadIdx.x;

    float v[8];
    float mx = -1e30f;
    #pragma unroll
    for (int i = 0; i < 8; i++) { v[i] = p[tid + i * 256]; mx = fmaxf(mx, v[i]); }

    __shared__ float red[256];
    red[tid] = mx;
    __syncthreads();
    for (int s = 128; s > 0; s >>= 1) {
        if (tid < s) red[tid] = fmaxf(red[tid], red[tid + s]);
        __syncthreads();
    }
    mx = red[0];
    __syncthreads();

    float sum = 0.f;
    #pragma unroll
    for (int i = 0; i < 8; i++) { v[i] = __expf(v[i] - mx); sum += v[i]; }
    red[tid] = sum;
    __syncthreads();
    for (int s = 128; s > 0; s >>= 1) {
        if (tid < s) red[tid] += red[tid + s];
        __syncthreads();
    }
    float inv = 1.f / red[0];
    #pragma unroll
    for (int i = 0; i < 8; i++) p[tid + i * 256] = v[i] * inv;
}

// ---------------------------------------------------------------------------
extern "C" void kernel_launch(void* const* d_in, const int* in_sizes, int n_in,
                              void* d_out, int out_size) {
    const float* q    = (const float*)d_in[0];
    const float* k    = (const float*)d_in[1];
    const float* v    = (const float*)d_in[2];
    const float* mask = (const float*)d_in[3];
    const float* Wq   = (const float*)d_in[4];
    const float* bq   = (const float*)d_in[5];
    const float* Wk   = (const float*)d_in[6];
    const float* bk   = (const float*)d_in[7];
    const float* Wv   = (const float*)d_in[8];
    const float* bv   = (const float*)d_in[9];
    const float* Wo   = (const float*)d_in[10];
    const float* bo   = (const float*)d_in[11];
    float* out = (float*)d_out;

    const size_t OUT_ELEMS  = (size_t)BS * Dd;
    const size_t ATTN_ELEMS = (size_t)BH * Ss * Ss;

    float* attnbuf = nullptr;
    cudaGetSymbolAddress((void**)&attnbuf, g_attn);
    if ((size_t)out_size >= OUT_ELEMS + ATTN_ELEMS) attnbuf = out + OUT_ELEMS;

    __nv_bfloat16 *dWth, *dWtl, *dQh, *dQl, *dKh, *dKl, *dVth, *dVtl, *dCh, *dCl;
    cudaGetSymbolAddress((void**)&dWth, g_Wth);
    cudaGetSymbolAddress((void**)&dWtl, g_Wtl);
    cudaGetSymbolAddress((void**)&dQh,  g_Qh);
    cudaGetSymbolAddress((void**)&dQl,  g_Ql);
    cudaGetSymbolAddress((void**)&dKh,  g_Kh);
    cudaGetSymbolAddress((void**)&dKl,  g_Kl);
    cudaGetSymbolAddress((void**)&dVth, g_Vth);
    cudaGetSymbolAddress((void**)&dVtl, g_Vtl);
    cudaGetSymbolAddress((void**)&dCh,  g_Ch);
    cudaGetSymbolAddress((void**)&dCl,  g_Cl);

    cudaFuncSetAttribute(proj_kernel<0>, cudaFuncAttributeMaxDynamicSharedMemorySize, SMEM_128);
    cudaFuncSetAttribute(proj_kernel<1>, cudaFuncAttributeMaxDynamicSharedMemorySize, SMEM_128);
    cudaFuncSetAttribute(logits_kernel,  cudaFuncAttributeMaxDynamicSharedMemorySize, SMEM_128);
    cudaFuncSetAttribute(ctx_kernel,     cudaFuncAttributeMaxDynamicSharedMemorySize, SMEM_64);

    dim3 tposeBlk(32, 32), tposeGrid(32, 32);
    dim3 projGrid(8, 64);

    // Q projection
    transpose_conv_kernel<<<tposeGrid, tposeBlk>>>(Wq, dWth, dWtl);
    proj_kernel<0><<<projGrid, 256, SMEM_128>>>(q, nullptr, nullptr, dWth, dWtl,
                                                bq, nullptr, dQh, dQl, 1);
    // K projection
    transpose_conv_kernel<<<tposeGrid, tposeBlk>>>(Wk, dWth, dWtl);
    proj_kernel<0><<<projGrid, 256, SMEM_128>>>(k, nullptr, nullptr, dWth, dWtl,
                                                bk, nullptr, dKh, dKl, 1);
    // V projection (writes V^T)
    transpose_conv_kernel<<<tposeGrid, tposeBlk>>>(Wv, dWth, dWtl);
    proj_kernel<0><<<projGrid, 256, SMEM_128>>>(v, nullptr, nullptr, dWth, dWtl,
                                                bv, nullptr, dVth, dVtl, 2);

    // logits + softmax
    logits_kernel<<<dim3(16, 16, 64), 256, SMEM_128>>>(dQh, dQl, dKh, dKl, mask, attnbuf);
    softmax_kernel<<<BH * Ss, 256>>>(attnbuf);

    // ctx (reads fp32 attn, converts inline)
    ctx_kernel<<<dim3(16, 64), 256, SMEM_64>>>(attnbuf, dVth, dVtl, dCh, dCl);

    // output projection
    transpose_conv_kernel<<<tposeGrid, tposeBlk>>>(Wo, dWth, dWtl);
    proj_kernel<1><<<projGrid, 256, SMEM_128>>>(nullptr, dCh, dCl, dWth, dWtl,
                                                bo, out, nullptr, nullptr, 0);
}